// round 12
// baseline (speedup 1.0000x reference)
#include <cuda_runtime.h>
#include <cuda_fp16.h>
#include <math.h>
#include <stdint.h>

#define NB 4096

// Scratch (device globals -- no allocation allowed)
__device__ float g_coef[NB * 8];
__device__ float g_h0[NB * 1024];
__device__ float g_h1[NB * 1024];
// fp16-packed, fragment-paired weights: [K/32][8][N] x uint2
//   { f16x2(W[k0],W[k0+1]), f16x2(W[k0+8],W[k0+9]) },  k0 = kt*32 + (p>>2)*16 + (p&3)*2
__device__ uint2 g_wp0[4608 / 4 * 1024];
__device__ uint2 g_wp1[8704 / 4 * 1024];
__device__ uint2 g_wp2[8704 / 4 * 512];

__device__ __forceinline__ float elu1(float x) {
    return x > 0.f ? x : expm1f(x);
}

__device__ __forceinline__ uint32_t f2h2(float lo, float hi) {
    __half2 h = __floats2half2_rn(lo, hi);   // .x = lo (low 16 bits), .y = hi
    return *(uint32_t*)&h;
}

__device__ __forceinline__ void cp16(uint32_t smem_addr, const void* gptr) {
    asm volatile("cp.async.cg.shared.global [%0], [%1], 16;\n"
                 :: "r"(smem_addr), "l"(gptr));
}
__device__ __forceinline__ void cp_commit() {
    asm volatile("cp.async.commit_group;\n" ::);
}
__device__ __forceinline__ void cp_wait1() {
    asm volatile("cp.async.wait_group 1;\n" ::);
}

__device__ __forceinline__ void mma_f16(float& d0, float& d1, float& d2, float& d3,
                                        uint32_t a0, uint32_t a1, uint32_t a2, uint32_t a3,
                                        uint32_t b0, uint32_t b1) {
    asm volatile(
        "mma.sync.aligned.m16n8k16.row.col.f32.f16.f16.f32 "
        "{%0,%1,%2,%3}, {%4,%5,%6,%7}, {%8,%9}, {%0,%1,%2,%3};\n"
        : "+f"(d0), "+f"(d1), "+f"(d2), "+f"(d3)
        : "r"(a0), "r"(a1), "r"(a2), "r"(a3), "r"(b0), "r"(b1));
}

// ---------------------------------------------------------------------------
// Weight pack (validated R9): W[k][n] -> [kt][p][n] uint2 of f16x2 pairs
// matching the m16n8k16 B-fragment: p = s*4 + t4, k0 = kt*32 + s*16 + t4*2.
// ---------------------------------------------------------------------------
template <int N>
__global__ __launch_bounds__(256) void pack_kernel(
    const float* __restrict__ W, uint2* __restrict__ Wp, int total)
{
    int idx = blockIdx.x * 256 + threadIdx.x;   // over (K/32)*8*N
    if (idx >= total) return;
    int n = idx % N;
    int r = idx / N;                 // kt*8 + p
    int kt = r >> 3, p = r & 7;
    int k0 = kt * 32 + (p >> 2) * 16 + (p & 3) * 2;
    uint2 v;
    v.x = f2h2(W[(size_t)k0 * N + n],       W[(size_t)(k0 + 1) * N + n]);
    v.y = f2h2(W[(size_t)(k0 + 8) * N + n], W[(size_t)(k0 + 9) * N + n]);
    Wp[idx] = v;
}

// ---------------------------------------------------------------------------
// Gate MLP (measured-fastest version, unchanged)
// ---------------------------------------------------------------------------
__global__ __launch_bounds__(128) void gate_kernel(
    const float* __restrict__ z, const float* __restrict__ c,
    const float* __restrict__ gw1, const float* __restrict__ gb1,
    const float* __restrict__ gw2, const float* __restrict__ gb2,
    const float* __restrict__ gw3, const float* __restrict__ gb3,
    float* __restrict__ coef)
{
    constexpr int R = 8;
    __shared__ float xs[R][576];
    __shared__ float h1s[R][128];
    __shared__ float h2s[R][128];
    __shared__ float lg[R][8];

    const int tid = threadIdx.x;
    const int b0 = blockIdx.x * R;

    for (int idx = tid; idx < R * 576; idx += 128) {
        int r = idx / 576;
        int i = idx - r * 576;
        xs[r][i] = (i < 64) ? z[(b0 + r) * 64 + i] : c[(b0 + r) * 512 + (i - 64)];
    }
    __syncthreads();

    float acc[R];
    {
        float bv = gb1[tid];
#pragma unroll
        for (int r = 0; r < R; r++) acc[r] = bv;
        for (int i = 0; i < 576; i++) {
            float w = gw1[i * 128 + tid];
#pragma unroll
            for (int r = 0; r < R; r++) acc[r] = fmaf(xs[r][i], w, acc[r]);
        }
#pragma unroll
        for (int r = 0; r < R; r++) h1s[r][tid] = elu1(acc[r]);
    }
    __syncthreads();

    {
        float bv = gb2[tid];
#pragma unroll
        for (int r = 0; r < R; r++) acc[r] = bv;
        for (int i = 0; i < 128; i++) {
            float w = gw2[i * 128 + tid];
#pragma unroll
            for (int r = 0; r < R; r++) acc[r] = fmaf(h1s[r][i], w, acc[r]);
        }
#pragma unroll
        for (int r = 0; r < R; r++) h2s[r][tid] = elu1(acc[r]);
    }
    __syncthreads();

    if (tid < 64) {
        int r = tid >> 3, e = tid & 7;
        float s = gb3[e];
        for (int i = 0; i < 128; i++) s = fmaf(h2s[r][i], gw3[i * 8 + e], s);
        lg[r][e] = s;
    }
    __syncthreads();

    if (tid < 64) {
        int r = tid >> 3, e = tid & 7;
        float mx = lg[r][0];
#pragma unroll
        for (int j = 1; j < 8; j++) mx = fmaxf(mx, lg[r][j]);
        float sum = 0.f;
#pragma unroll
        for (int j = 0; j < 8; j++) sum += expf(lg[r][j] - mx);
        coef[(b0 + r) * 8 + e] = expf(lg[r][e] - mx) / sum;
    }
}

// ---------------------------------------------------------------------------
// Mixed layer fp16 GEMM (fp32 accum), m16n8k16. R9 pipeline (3-stage ring,
// single barrier per k-tile). DELTA vs R9: A staged as coef-scaled fp16
// (LDG -> FMUL -> cvt -> STS, hoisted off the compute path) so the mainloop
// A fragment is a bare LDS.32 -> MMA chain: no FMUL/cvt in the loop.
//   A layout: 128 rows x 16 f16x2 pairs, row stride 20 u32 (banks injective
//   over lanes: 20*g8 + t4 mod 32 distinct for g8<8, t4<4).
//   B: pre-packed f16x2 fragment pairs (validated), 1 LDS.64 per fragment.
// ---------------------------------------------------------------------------
template <int XC, int N, int BN, bool ELU>
__global__ __launch_bounds__(256, 2) void mixed_tc_kernel(
    const float* __restrict__ z,
    const float* __restrict__ xp,
    const uint2* __restrict__ Wp,
    const float* __restrict__ bias,
    const float* __restrict__ coef,
    float* __restrict__ out)
{
    constexpr int BM = 128;
    constexpr int BK = 32;
    constexpr int IN = 64 + XC;
    constexpr int K = 8 * IN;
    constexpr int NT = K / BK;
    constexpr int NS = 3;           // pipeline stages
    constexpr int ASTp = 20;        // A row stride in u32 (16 pairs + 4 pad)
    constexpr int BNp = BN + 4;     // B pair-row stride (uint2); % 16 == 4 -> LDS.64 ok
    constexpr int WN = BN / 2;
    constexpr int NTN = WN / 8;

    extern __shared__ char smraw[];
    uint32_t* Ah = (uint32_t*)smraw;               // NS * BM * ASTp u32 (f16x2 pairs)
    uint2* Bp = (uint2*)(Ah + NS * BM * ASTp);     // NS * 8 * BNp uint2
    float* coefS = (float*)(Bp + NS * 8 * BNp);    // BM * 9
    float* biasS = coefS + BM * 9;                 // 8 * BN

    const int tid = threadIdx.x;
    const int m0 = blockIdx.y * BM;
    const int n0 = blockIdx.x * BN;
    const int w = tid >> 5, lane = tid & 31;
    const int wm0 = (w & 3) * 32;
    const int wn0 = (w >> 2) * WN;
    const int g8 = lane >> 2;
    const int t4 = lane & 3;

    // --- A staging: thread -> (row = tid>>1, k-half = tid&1), 16 floats ---
    const int arow = tid >> 1;
    const int ahalf = tid & 1;
    float4 ra[4];

    auto ldgA = [&](int kt) {
        const int e = (kt * BK) / IN;
        const int i0 = kt * BK - e * IN;
        const float* base;
        if (i0 < 64) base = z + (size_t)(m0 + arow) * 64 + i0 + ahalf * 16;
        else         base = xp + (size_t)(m0 + arow) * XC + (i0 - 64) + ahalf * 16;
#pragma unroll
        for (int j = 0; j < 4; j++)
            ra[j] = *(const float4*)(base + j * 4);
    };
    auto stsA = [&](int kt, int stg) {
        const int e = (kt * BK) / IN;
        const float cf = coefS[arow * 9 + e];
        uint32_t* dst = Ah + stg * BM * ASTp + arow * ASTp + ahalf * 8;
#pragma unroll
        for (int j = 0; j < 4; j++) {
            uint2 v;
            v.x = f2h2(ra[j].x * cf, ra[j].y * cf);
            v.y = f2h2(ra[j].z * cf, ra[j].w * cf);
            *(uint2*)(dst + j * 2) = v;
        }
    };

    // --- B staging: 8 pair-rows x BN uint2 per stage = 4*BN 16B chunks ---
    auto cpB = [&](int kt, int stg) {
        uint32_t dbase = (uint32_t)__cvta_generic_to_shared(Bp + stg * 8 * BNp);
        const uint2* src = Wp + (size_t)kt * 8 * N + n0;
        constexpr int CPR = BN / 2;              // 16B chunks per row
        constexpr int CHUNKS = 8 * CPR;          // 512 (BN=128) or 256 (BN=64)
#pragma unroll
        for (int j = 0; j < CHUNKS / 256; j++) {
            int idx = j * 256 + tid;
            int r = idx / CPR;
            int c16 = idx - r * CPR;
            cp16(dbase + (r * BNp + c16 * 2) * 8, src + (size_t)r * N + c16 * 2);
        }
    };

    // --- prologue ---
    cpB(0, 0);
    cp_commit();
    cpB(1, 1);
    cp_commit();

    for (int idx = tid; idx < BM * 8; idx += 256)
        coefS[(idx >> 3) * 9 + (idx & 7)] = coef[(size_t)(m0 + (idx >> 3)) * 8 + (idx & 7)];
    for (int idx = tid; idx < 8 * BN; idx += 256) {
        int e = idx / BN, cn = idx - e * BN;
        biasS[e * BN + cn] = bias[(size_t)e * N + n0 + cn];
    }
    __syncthreads();            // coefS visible before stsA(0)

    ldgA(0);
    stsA(0, 0);                 // buffer 0: untouched, safe pre-loop
    ldgA(1);                    // ra holds tile 1 for stsA at iter 0

    float acc[2][NTN][4];
#pragma unroll
    for (int mt = 0; mt < 2; mt++)
#pragma unroll
        for (int nt = 0; nt < NTN; nt++)
#pragma unroll
            for (int q = 0; q < 4; q++) acc[mt][nt][q] = 0.f;

    int buf = 0;
    for (int kt = 0; kt < NT; kt++) {
        cp_wait1();             // B group kt complete (kt+1 still flying)
        __syncthreads();        // visibility + all warps done with compute(kt-1)

        // stage A(kt+1) into buffer (kt+1)%NS == (kt-2)%NS (freed at barrier kt-1)
        const int nb1 = (buf == NS - 1) ? 0 : buf + 1;
        if (kt + 1 < NT) stsA(kt + 1, nb1);
        // B(kt+2) into buffer (kt+2)%NS == (kt-1)%NS (freed at this barrier)
        const int nb2 = (nb1 == NS - 1) ? 0 : nb1 + 1;
        if (kt + 2 < NT) cpB(kt + 2, nb2);
        cp_commit();            // one group per iteration (possibly empty)
        if (kt + 2 < NT) ldgA(kt + 2);   // LDG latency covered by compute below

        const uint32_t* Ab = Ah + buf * BM * ASTp;
        const uint2* Bb = Bp + buf * 8 * BNp;

#pragma unroll
        for (int s = 0; s < 2; s++) {           // two k16 steps per BK=32
            uint32_t af[2][4];
#pragma unroll
            for (int mt = 0; mt < 2; mt++) {
                const int r0 = wm0 + mt * 16 + g8;
                af[mt][0] = Ab[r0 * ASTp + s * 8 + t4];
                af[mt][1] = Ab[(r0 + 8) * ASTp + s * 8 + t4];
                af[mt][2] = Ab[r0 * ASTp + s * 8 + t4 + 4];
                af[mt][3] = Ab[(r0 + 8) * ASTp + s * 8 + t4 + 4];
            }
#pragma unroll
            for (int nt = 0; nt < NTN; nt++) {
                const int cn = wn0 + nt * 8 + g8;
                uint2 bp = Bb[(s * 4 + t4) * BNp + cn];
#pragma unroll
                for (int mt = 0; mt < 2; mt++)
                    mma_f16(acc[mt][nt][0], acc[mt][nt][1], acc[mt][nt][2], acc[mt][nt][3],
                            af[mt][0], af[mt][1], af[mt][2], af[mt][3], bp.x, bp.y);
            }
        }

        buf = nb1;
    }

    // --- epilogue: + coef·bias, activation, store ---
#pragma unroll
    for (int mt = 0; mt < 2; mt++) {
#pragma unroll
        for (int half = 0; half < 2; half++) {
            const int rl = wm0 + mt * 16 + g8 + half * 8;
            float cfr[8];
#pragma unroll
            for (int e2 = 0; e2 < 8; e2++) cfr[e2] = coefS[rl * 9 + e2];
            float* orow = out + (size_t)(m0 + rl) * N + n0;
#pragma unroll
            for (int nt = 0; nt < NTN; nt++) {
                const int cl = wn0 + nt * 8 + t4 * 2;
                float v0 = acc[mt][nt][half * 2 + 0];
                float v1 = acc[mt][nt][half * 2 + 1];
#pragma unroll
                for (int e2 = 0; e2 < 8; e2++) {
                    v0 = fmaf(cfr[e2], biasS[e2 * BN + cl], v0);
                    v1 = fmaf(cfr[e2], biasS[e2 * BN + cl + 1], v1);
                }
                if (ELU) { v0 = elu1(v0); v1 = elu1(v1); }
                *(float2*)(orow + cl) = make_float2(v0, v1);
            }
        }
    }
}

// ---------------------------------------------------------------------------

static constexpr int smem_bytes(int BN) {
    return 3 * 128 * 20 * 4 + 3 * 8 * (BN + 4) * 8 + (128 * 9 + 8 * BN) * 4;
}

extern "C" void kernel_launch(void* const* d_in, const int* in_sizes, int n_in,
                              void* d_out, int out_size)
{
    const float* z   = (const float*)d_in[0];
    const float* c   = (const float*)d_in[1];
    const float* w0  = (const float*)d_in[2];
    const float* b0  = (const float*)d_in[3];
    const float* w1  = (const float*)d_in[4];
    const float* b1  = (const float*)d_in[5];
    const float* w2  = (const float*)d_in[6];
    const float* b2  = (const float*)d_in[7];
    const float* gw1 = (const float*)d_in[8];
    const float* gb1 = (const float*)d_in[9];
    const float* gw2 = (const float*)d_in[10];
    const float* gb2 = (const float*)d_in[11];
    const float* gw3 = (const float*)d_in[12];
    const float* gb3 = (const float*)d_in[13];

    float *coef, *h0, *h1;
    uint2 *wp0, *wp1, *wp2;
    cudaGetSymbolAddress((void**)&coef, g_coef);
    cudaGetSymbolAddress((void**)&h0, g_h0);
    cudaGetSymbolAddress((void**)&h1, g_h1);
    cudaGetSymbolAddress((void**)&wp0, g_wp0);
    cudaGetSymbolAddress((void**)&wp1, g_wp1);
    cudaGetSymbolAddress((void**)&wp2, g_wp2);

    cudaFuncSetAttribute(mixed_tc_kernel<512, 1024, 128, true>,
                         cudaFuncAttributeMaxDynamicSharedMemorySize, smem_bytes(128));
    cudaFuncSetAttribute(mixed_tc_kernel<1024, 1024, 128, true>,
                         cudaFuncAttributeMaxDynamicSharedMemorySize, smem_bytes(128));
    cudaFuncSetAttribute(mixed_tc_kernel<1024, 512, 64, false>,
                         cudaFuncAttributeMaxDynamicSharedMemorySize, smem_bytes(64));

    // pack weights to f16x2 fragment-pair layout
    {
        int t0 = 4608 / 4 * 1024;
        int t1 = 8704 / 4 * 1024;
        int t2 = 8704 / 4 * 512;
        pack_kernel<1024><<<(t0 + 255) / 256, 256>>>(w0, wp0, t0);
        pack_kernel<1024><<<(t1 + 255) / 256, 256>>>(w1, wp1, t1);
        pack_kernel<512><<<(t2 + 255) / 256, 256>>>(w2, wp2, t2);
    }

    gate_kernel<<<NB / 8, 128>>>(z, c, gw1, gb1, gw2, gb2, gw3, gb3, coef);

    // layer0: M=4096, K=4608, N=1024
    mixed_tc_kernel<512, 1024, 128, true>
        <<<dim3(1024 / 128, NB / 128), 256, smem_bytes(128)>>>(z, c, wp0, b0, coef, h0);

    // layer1: M=4096, K=8704, N=1024
    mixed_tc_kernel<1024, 1024, 128, true>
        <<<dim3(1024 / 128, NB / 128), 256, smem_bytes(128)>>>(z, h0, wp1, b1, coef, h1);

    // layer2: M=4096, K=8704, N=512
    mixed_tc_kernel<1024, 512, 64, false>
        <<<dim3(512 / 64, NB / 128), 256, smem_bytes(64)>>>(z, h1, wp2, b2, coef, (float*)d_out);
}

// round 13
// speedup vs baseline: 2.3899x; 2.3899x over previous
#include <cuda_runtime.h>
#include <cuda_fp16.h>
#include <math.h>
#include <stdint.h>

#define NB 4096

// Scratch (device globals -- no allocation allowed)
__device__ float g_coef[NB * 8];
__device__ float g_h0[NB * 1024];
__device__ float g_h1[NB * 1024];
// coef-scaled fp16 A, [B][K] k-order, reused across layers (max K = 8704)
__device__ __half g_aexp[(size_t)NB * 8704];
// fp16-packed, fragment-paired weights: [K/32][8][N] x uint2
//   { f16x2(W[k0],W[k0+1]), f16x2(W[k0+8],W[k0+9]) },  k0 = kt*32 + (p>>2)*16 + (p&3)*2
__device__ uint2 g_wp0[4608 / 4 * 1024];
__device__ uint2 g_wp1[8704 / 4 * 1024];
__device__ uint2 g_wp2[8704 / 4 * 512];

__device__ __forceinline__ float elu1(float x) {
    return x > 0.f ? x : expm1f(x);
}

__device__ __forceinline__ uint32_t f2h2(float lo, float hi) {
    __half2 h = __floats2half2_rn(lo, hi);   // .x = lo (low 16 bits), .y = hi
    return *(uint32_t*)&h;
}

__device__ __forceinline__ void cp16(uint32_t smem_addr, const void* gptr) {
    asm volatile("cp.async.cg.shared.global [%0], [%1], 16;\n"
                 :: "r"(smem_addr), "l"(gptr));
}
__device__ __forceinline__ void cp_commit() {
    asm volatile("cp.async.commit_group;\n" ::);
}
__device__ __forceinline__ void cp_wait1() {
    asm volatile("cp.async.wait_group 1;\n" ::);
}

__device__ __forceinline__ void mma_f16(float& d0, float& d1, float& d2, float& d3,
                                        uint32_t a0, uint32_t a1, uint32_t a2, uint32_t a3,
                                        uint32_t b0, uint32_t b1) {
    asm volatile(
        "mma.sync.aligned.m16n8k16.row.col.f32.f16.f16.f32 "
        "{%0,%1,%2,%3}, {%4,%5,%6,%7}, {%8,%9}, {%0,%1,%2,%3};\n"
        : "+f"(d0), "+f"(d1), "+f"(d2), "+f"(d3)
        : "r"(a0), "r"(a1), "r"(a2), "r"(a3), "r"(b0), "r"(b1));
}

// ---------------------------------------------------------------------------
// Weight pack (validated R9): W[k][n] -> [kt][p][n] uint2 of f16x2 pairs
// matching the m16n8k16 B-fragment: p = s*4 + t4, k0 = kt*32 + s*16 + t4*2.
// ---------------------------------------------------------------------------
template <int N>
__global__ __launch_bounds__(256) void pack_kernel(
    const float* __restrict__ W, uint2* __restrict__ Wp, int total)
{
    int idx = blockIdx.x * 256 + threadIdx.x;   // over (K/32)*8*N
    if (idx >= total) return;
    int n = idx % N;
    int r = idx / N;                 // kt*8 + p
    int kt = r >> 3, p = r & 7;
    int k0 = kt * 32 + (p >> 2) * 16 + (p & 3) * 2;
    uint2 v;
    v.x = f2h2(W[(size_t)k0 * N + n],       W[(size_t)(k0 + 1) * N + n]);
    v.y = f2h2(W[(size_t)(k0 + 8) * N + n], W[(size_t)(k0 + 9) * N + n]);
    Wp[idx] = v;
}

// ---------------------------------------------------------------------------
// A expansion: Aexp[b][k] = half(coef[b,e(k)] * x[b,i(k)]), k-order fp16.
// One 16B chunk (8 halves) per thread; chunk never crosses expert or z/xp
// boundary (both multiples of 8). Same rounding points as R9's in-loop path.
// ---------------------------------------------------------------------------
template <int XC>
__global__ __launch_bounds__(256) void expand_kernel(
    const float* __restrict__ z, const float* __restrict__ xp,
    const float* __restrict__ coef, __half* __restrict__ Aexp, int total)
{
    constexpr int IN = 64 + XC;
    constexpr int K = 8 * IN;
    constexpr int CK = K / 8;           // chunks per batch row
    int idx = blockIdx.x * 256 + threadIdx.x;
    if (idx >= total) return;
    int b = idx / CK;
    int ck = idx - b * CK;
    int k0 = ck * 8;
    int e = k0 / IN;
    int i0 = k0 - e * IN;
    float cf = coef[b * 8 + e];
    const float* src = (i0 < 64) ? z + (size_t)b * 64 + i0
                                 : xp + (size_t)b * XC + (i0 - 64);
    float4 a = *(const float4*)src;
    float4 q = *(const float4*)(src + 4);
    uint4 h;
    h.x = f2h2(a.x * cf, a.y * cf);
    h.y = f2h2(a.z * cf, a.w * cf);
    h.z = f2h2(q.x * cf, q.y * cf);
    h.w = f2h2(q.z * cf, q.w * cf);
    *(uint4*)(Aexp + (size_t)b * K + k0) = h;
}

// ---------------------------------------------------------------------------
// Gate MLP (measured-fastest version, unchanged)
// ---------------------------------------------------------------------------
__global__ __launch_bounds__(128) void gate_kernel(
    const float* __restrict__ z, const float* __restrict__ c,
    const float* __restrict__ gw1, const float* __restrict__ gb1,
    const float* __restrict__ gw2, const float* __restrict__ gb2,
    const float* __restrict__ gw3, const float* __restrict__ gb3,
    float* __restrict__ coef)
{
    constexpr int R = 8;
    __shared__ float xs[R][576];
    __shared__ float h1s[R][128];
    __shared__ float h2s[R][128];
    __shared__ float lg[R][8];

    const int tid = threadIdx.x;
    const int b0 = blockIdx.x * R;

    for (int idx = tid; idx < R * 576; idx += 128) {
        int r = idx / 576;
        int i = idx - r * 576;
        xs[r][i] = (i < 64) ? z[(b0 + r) * 64 + i] : c[(b0 + r) * 512 + (i - 64)];
    }
    __syncthreads();

    float acc[R];
    {
        float bv = gb1[tid];
#pragma unroll
        for (int r = 0; r < R; r++) acc[r] = bv;
        for (int i = 0; i < 576; i++) {
            float w = gw1[i * 128 + tid];
#pragma unroll
            for (int r = 0; r < R; r++) acc[r] = fmaf(xs[r][i], w, acc[r]);
        }
#pragma unroll
        for (int r = 0; r < R; r++) h1s[r][tid] = elu1(acc[r]);
    }
    __syncthreads();

    {
        float bv = gb2[tid];
#pragma unroll
        for (int r = 0; r < R; r++) acc[r] = bv;
        for (int i = 0; i < 128; i++) {
            float w = gw2[i * 128 + tid];
#pragma unroll
            for (int r = 0; r < R; r++) acc[r] = fmaf(h1s[r][i], w, acc[r]);
        }
#pragma unroll
        for (int r = 0; r < R; r++) h2s[r][tid] = elu1(acc[r]);
    }
    __syncthreads();

    if (tid < 64) {
        int r = tid >> 3, e = tid & 7;
        float s = gb3[e];
        for (int i = 0; i < 128; i++) s = fmaf(h2s[r][i], gw3[i * 8 + e], s);
        lg[r][e] = s;
    }
    __syncthreads();

    if (tid < 64) {
        int r = tid >> 3, e = tid & 7;
        float mx = lg[r][0];
#pragma unroll
        for (int j = 1; j < 8; j++) mx = fmaxf(mx, lg[r][j]);
        float sum = 0.f;
#pragma unroll
        for (int j = 0; j < 8; j++) sum += expf(lg[r][j] - mx);
        coef[(b0 + r) * 8 + e] = expf(lg[r][e] - mx) / sum;
    }
}

// ---------------------------------------------------------------------------
// Mixed layer fp16 GEMM (fp32 accum), m16n8k16. R9 pipeline EXACTLY (3-stage
// cp.async ring, wait_group 1, one barrier per k-tile). DELTA vs R9: A comes
// pre-scaled fp16 from Aexp via cp.async -> mainloop A fragment is a bare
// LDS.32 -> MMA chain (no FMUL/CVT in loop, no staging registers).
//   A smem: 128 rows x 32 halves, row stride 40 halves (80B) ->
//   u32-bank(20*g8 + t4) bijective over the 32 banks: conflict-free.
// ---------------------------------------------------------------------------
template <int XC, int N, int BN, bool ELU>
__global__ __launch_bounds__(256, 2) void mixed_tc_kernel(
    const __half* __restrict__ Aexp,
    const uint2* __restrict__ Wp,
    const float* __restrict__ bias,
    const float* __restrict__ coef,
    float* __restrict__ out)
{
    constexpr int BM = 128;
    constexpr int BK = 32;
    constexpr int IN = 64 + XC;
    constexpr int K = 8 * IN;
    constexpr int NT = K / BK;
    constexpr int NS = 3;           // pipeline stages
    constexpr int ASTu = 20;        // A row stride in u32 (16 f16x2 + 4 pad)
    constexpr int BNp = BN + 4;     // B pair-row stride (uint2); % 16 == 4 -> LDS.64 ok
    constexpr int WN = BN / 2;
    constexpr int NTN = WN / 8;

    extern __shared__ char smraw[];
    uint32_t* Ah = (uint32_t*)smraw;               // NS * BM * ASTu u32
    uint2* Bp = (uint2*)(Ah + NS * BM * ASTu);     // NS * 8 * BNp uint2
    float* coefS = (float*)(Bp + NS * 8 * BNp);    // BM * 9
    float* biasS = coefS + BM * 9;                 // 8 * BN

    const int tid = threadIdx.x;
    const int m0 = blockIdx.y * BM;
    const int n0 = blockIdx.x * BN;
    const int w = tid >> 5, lane = tid & 31;
    const int wm0 = (w & 3) * 32;
    const int wn0 = (w >> 2) * WN;
    const int g8 = lane >> 2;
    const int t4 = lane & 3;

    // --- A staging: pure cp.async of pre-scaled fp16 (4 chunks/row) ---
    auto cpA = [&](int kt, int stg) {
        uint32_t dbase = (uint32_t)__cvta_generic_to_shared(Ah + stg * BM * ASTu);
        const __half* src = Aexp + (size_t)m0 * K + kt * BK;
#pragma unroll
        for (int j = 0; j < 2; j++) {
            int idx = j * 256 + tid;
            int row = idx >> 2;
            int ch = idx & 3;
            cp16(dbase + row * 80 + ch * 16, src + (size_t)row * K + ch * 8);
        }
    };

    // --- B staging: 8 pair-rows x BN uint2 per stage = 4*BN 16B chunks ---
    auto cpB = [&](int kt, int stg) {
        uint32_t dbase = (uint32_t)__cvta_generic_to_shared(Bp + stg * 8 * BNp);
        const uint2* src = Wp + (size_t)kt * 8 * N + n0;
        constexpr int CPR = BN / 2;              // 16B chunks per row
        constexpr int CHUNKS = 8 * CPR;          // 512 (BN=128) or 256 (BN=64)
#pragma unroll
        for (int j = 0; j < CHUNKS / 256; j++) {
            int idx = j * 256 + tid;
            int r = idx / CPR;
            int c16 = idx - r * CPR;
            cp16(dbase + (r * BNp + c16 * 2) * 8, src + (size_t)r * N + c16 * 2);
        }
    };

    // --- prologue: stages 0 and 1 in flight as separate groups ---
    cpA(0, 0);
    cpB(0, 0);
    cp_commit();
    cpA(1, 1);
    cpB(1, 1);
    cp_commit();

    for (int idx = tid; idx < BM * 8; idx += 256)
        coefS[(idx >> 3) * 9 + (idx & 7)] = coef[(size_t)(m0 + (idx >> 3)) * 8 + (idx & 7)];
    for (int idx = tid; idx < 8 * BN; idx += 256) {
        int e = idx / BN, cn = idx - e * BN;
        biasS[e * BN + cn] = bias[(size_t)e * N + n0 + cn];
    }

    float acc[2][NTN][4];
#pragma unroll
    for (int mt = 0; mt < 2; mt++)
#pragma unroll
        for (int nt = 0; nt < NTN; nt++)
#pragma unroll
            for (int q = 0; q < 4; q++) acc[mt][nt][q] = 0.f;

    int buf = 0;        // stage being computed (kt % NS)
    int nbuf = 2;       // stage being filled  ((kt+2) % NS)
    for (int kt = 0; kt < NT; kt++) {
        cp_wait1();             // stage kt's group complete (kt+1 still flying)
        __syncthreads();        // visibility + all warps done with compute(kt-1)

        const uint32_t* Ab = Ah + buf * BM * ASTu;
        const uint2* Bb = Bp + buf * 8 * BNp;

#pragma unroll
        for (int s = 0; s < 2; s++) {           // two k16 steps per BK=32
            uint32_t af[2][4];
#pragma unroll
            for (int mt = 0; mt < 2; mt++) {
                const int r0 = wm0 + mt * 16 + g8;
                af[mt][0] = Ab[r0 * ASTu + s * 8 + t4];
                af[mt][1] = Ab[(r0 + 8) * ASTu + s * 8 + t4];
                af[mt][2] = Ab[r0 * ASTu + s * 8 + t4 + 4];
                af[mt][3] = Ab[(r0 + 8) * ASTu + s * 8 + t4 + 4];
            }
#pragma unroll
            for (int nt = 0; nt < NTN; nt++) {
                const int cn = wn0 + nt * 8 + g8;
                uint2 bp = Bb[(s * 4 + t4) * BNp + cn];
#pragma unroll
                for (int mt = 0; mt < 2; mt++)
                    mma_f16(acc[mt][nt][0], acc[mt][nt][1], acc[mt][nt][2], acc[mt][nt][3],
                            af[mt][0], af[mt][1], af[mt][2], af[mt][3], bp.x, bp.y);
            }
        }

        if (kt + 2 < NT) { cpA(kt + 2, nbuf); cpB(kt + 2, nbuf); }
        cp_commit();            // one group per iteration (possibly empty at tail)

        buf = (buf == NS - 1) ? 0 : buf + 1;
        nbuf = (nbuf == NS - 1) ? 0 : nbuf + 1;
    }

    // --- epilogue: + coef·bias, activation, store ---
#pragma unroll
    for (int mt = 0; mt < 2; mt++) {
#pragma unroll
        for (int half = 0; half < 2; half++) {
            const int rl = wm0 + mt * 16 + g8 + half * 8;
            float cfr[8];
#pragma unroll
            for (int e2 = 0; e2 < 8; e2++) cfr[e2] = coefS[rl * 9 + e2];
            float* orow = out + (size_t)(m0 + rl) * N + n0;
#pragma unroll
            for (int nt = 0; nt < NTN; nt++) {
                const int cl = wn0 + nt * 8 + t4 * 2;
                float v0 = acc[mt][nt][half * 2 + 0];
                float v1 = acc[mt][nt][half * 2 + 1];
#pragma unroll
                for (int e2 = 0; e2 < 8; e2++) {
                    v0 = fmaf(cfr[e2], biasS[e2 * BN + cl], v0);
                    v1 = fmaf(cfr[e2], biasS[e2 * BN + cl + 1], v1);
                }
                if (ELU) { v0 = elu1(v0); v1 = elu1(v1); }
                *(float2*)(orow + cl) = make_float2(v0, v1);
            }
        }
    }
}

// ---------------------------------------------------------------------------

static constexpr int smem_bytes(int BN) {
    return 3 * 128 * 20 * 4 + 3 * 8 * (BN + 4) * 8 + (128 * 9 + 8 * BN) * 4;
}

extern "C" void kernel_launch(void* const* d_in, const int* in_sizes, int n_in,
                              void* d_out, int out_size)
{
    const float* z   = (const float*)d_in[0];
    const float* c   = (const float*)d_in[1];
    const float* w0  = (const float*)d_in[2];
    const float* b0  = (const float*)d_in[3];
    const float* w1  = (const float*)d_in[4];
    const float* b1  = (const float*)d_in[5];
    const float* w2  = (const float*)d_in[6];
    const float* b2  = (const float*)d_in[7];
    const float* gw1 = (const float*)d_in[8];
    const float* gb1 = (const float*)d_in[9];
    const float* gw2 = (const float*)d_in[10];
    const float* gb2 = (const float*)d_in[11];
    const float* gw3 = (const float*)d_in[12];
    const float* gb3 = (const float*)d_in[13];

    float *coef, *h0, *h1;
    __half* aexp;
    uint2 *wp0, *wp1, *wp2;
    cudaGetSymbolAddress((void**)&coef, g_coef);
    cudaGetSymbolAddress((void**)&h0, g_h0);
    cudaGetSymbolAddress((void**)&h1, g_h1);
    cudaGetSymbolAddress((void**)&aexp, g_aexp);
    cudaGetSymbolAddress((void**)&wp0, g_wp0);
    cudaGetSymbolAddress((void**)&wp1, g_wp1);
    cudaGetSymbolAddress((void**)&wp2, g_wp2);

    cudaFuncSetAttribute(mixed_tc_kernel<512, 1024, 128, true>,
                         cudaFuncAttributeMaxDynamicSharedMemorySize, smem_bytes(128));
    cudaFuncSetAttribute(mixed_tc_kernel<1024, 1024, 128, true>,
                         cudaFuncAttributeMaxDynamicSharedMemorySize, smem_bytes(128));
    cudaFuncSetAttribute(mixed_tc_kernel<1024, 512, 64, false>,
                         cudaFuncAttributeMaxDynamicSharedMemorySize, smem_bytes(64));

    // pack weights to f16x2 fragment-pair layout
    {
        int t0 = 4608 / 4 * 1024;
        int t1 = 8704 / 4 * 1024;
        int t2 = 8704 / 4 * 512;
        pack_kernel<1024><<<(t0 + 255) / 256, 256>>>(w0, wp0, t0);
        pack_kernel<1024><<<(t1 + 255) / 256, 256>>>(w1, wp1, t1);
        pack_kernel<512><<<(t2 + 255) / 256, 256>>>(w2, wp2, t2);
    }

    gate_kernel<<<NB / 8, 128>>>(z, c, gw1, gb1, gw2, gb2, gw3, gb3, coef);

    const int ta = NB * (4608 / 8);
    const int tb = NB * (8704 / 8);

    // layer0: M=4096, K=4608, N=1024
    expand_kernel<512><<<(ta + 255) / 256, 256>>>(z, c, coef, aexp, ta);
    mixed_tc_kernel<512, 1024, 128, true>
        <<<dim3(1024 / 128, NB / 128), 256, smem_bytes(128)>>>(aexp, wp0, b0, coef, h0);

    // layer1: M=4096, K=8704, N=1024
    expand_kernel<1024><<<(tb + 255) / 256, 256>>>(z, h0, coef, aexp, tb);
    mixed_tc_kernel<1024, 1024, 128, true>
        <<<dim3(1024 / 128, NB / 128), 256, smem_bytes(128)>>>(aexp, wp1, b1, coef, h1);

    // layer2: M=4096, K=8704, N=512
    expand_kernel<1024><<<(tb + 255) / 256, 256>>>(z, h1, coef, aexp, tb);
    mixed_tc_kernel<1024, 512, 64, false>
        <<<dim3(512 / 64, NB / 128), 256, smem_bytes(64)>>>(aexp, wp2, b2, coef, (float*)d_out);
}